// round 16
// baseline (speedup 1.0000x reference)
#include <cuda_runtime.h>
#include <cuda_fp16.h>

#define Dd  512
#define Sd  512
#define Bd  2
#define Hd  8
#define HDd 64

typedef unsigned long long u64;
typedef unsigned int u32;

// ---------------- scratch (device globals) ----------------
__device__ __half g_Wqh[Dd * Dd];       // folded Wq@Aq, transposed [n][k], f16
__device__ __half g_Wkh[Dd * Dd];       // folded Wk@Ak, transposed [n][k], f16
__device__ __half g_Wvh[Dd * Dd];       // Wv transposed [n][k], f16
__device__ __half g_Woh[Dd * Dd];       // Wo transposed [n][k], f16
__device__ float  g_bq[Dd];
__device__ float  g_bk[Dd];
__device__ __half g_xq16[Bd * Sd * Dd];
__device__ __half g_xk16[Bd * Sd * Dd];
__device__ __half g_xv16[Bd * Sd * Dd];
__device__ __half g_qth[Bd * Sd * Dd];  // q_term f16, row-major
__device__ __half g_kth[Bd * Sd * Dd];  // k_term f16
__device__ __half g_v16T[Bd * Hd * HDd * Sd]; // v, per (b,h) transposed [d][s]
__device__ __half g_ctx16[Bd * Sd * Dd];      // ctx f16, row-major

// ---------------- asm helpers ----------------
__device__ __forceinline__ void h2f2(u32 h, float& lo, float& hi) {
    asm("{ .reg .b16 l, h;\n\t mov.b32 {l, h}, %2;\n\t"
        " cvt.f32.f16 %0, l;\n\t cvt.f32.f16 %1, h; }"
        : "=f"(lo), "=f"(hi) : "r"(h));
}
__device__ __forceinline__ void tchain(u32 q2, u32 k2, u32 a2, u32& acch) {
    u32 x2, t2;
    asm("add.rn.f16x2 %0, %1, %2;" : "=r"(x2) : "r"(q2), "r"(k2));
    asm("tanh.approx.f16x2 %0, %1;" : "=r"(t2) : "r"(x2));
    asm("fma.rn.f16x2 %0, %1, %2, %0;" : "+r"(acch) : "r"(t2), "r"(a2));
}
__device__ __forceinline__ u32 hadd2u(u32 a, u32 b) {
    u32 r;
    asm("add.rn.f16x2 %0, %1, %2;" : "=r"(r) : "r"(a), "r"(b));
    return r;
}
__device__ __forceinline__ void mma16816(float* d, const u32* a, const u32* b) {
    asm volatile(
        "mma.sync.aligned.m16n8k16.row.col.f32.f16.f16.f32 "
        "{%0,%1,%2,%3}, {%4,%5,%6,%7}, {%8,%9}, {%0,%1,%2,%3};"
        : "+f"(d[0]), "+f"(d[1]), "+f"(d[2]), "+f"(d[3])
        : "r"(a[0]), "r"(a[1]), "r"(a[2]), "r"(a[3]), "r"(b[0]), "r"(b[1]));
}
__device__ __forceinline__ void ldsm4(u32& r0, u32& r1, u32& r2, u32& r3, u32 addr) {
    asm volatile("ldmatrix.sync.aligned.m8n8.x4.shared.b16 {%0,%1,%2,%3}, [%4];"
                 : "=r"(r0), "=r"(r1), "=r"(r2), "=r"(r3) : "r"(addr));
}
__device__ __forceinline__ void cp16(u32 dst, const void* src) {
    asm volatile("cp.async.cg.shared.global [%0], [%1], 16;" :: "r"(dst), "l"(src));
}

// ---------------- fused prep + fold (unchanged) ----------------
__global__ __launch_bounds__(256) void prep_fold_kernel(
        const float* __restrict__ q, const float* __restrict__ k,
        const float* __restrict__ v,
        const float* __restrict__ Wv, const float* __restrict__ Wo,
        const float* __restrict__ Wq, const float* __restrict__ Aq,
        const float* __restrict__ bqi,
        const float* __restrict__ Wk, const float* __restrict__ Ak,
        const float* __restrict__ bki) {
    __shared__ float pool[8512];
    int bx = blockIdx.x, tid = threadIdx.x;

    if (bx < 768) {
        int t = bx * 256 + tid;
        int sel = t >> 16;
        const float* src = (sel == 0) ? q : (sel == 1) ? k : v;
        __half* dst = (sel == 0) ? g_xq16 : (sel == 1) ? g_xk16 : g_xv16;
        int base = (t & 65535) * 8;
        float4 a = *(const float4*)(src + base);
        float4 b = *(const float4*)(src + base + 4);
        __half2 h0 = __floats2half2_rn(a.x, a.y), h1 = __floats2half2_rn(a.z, a.w);
        __half2 h2 = __floats2half2_rn(b.x, b.y), h3 = __floats2half2_rn(b.z, b.w);
        uint4 u;
        u.x = *(u32*)&h0; u.y = *(u32*)&h1; u.z = *(u32*)&h2; u.w = *(u32*)&h3;
        *(uint4*)(dst + base) = u;
    } else if (bx < 1280) {
        float (*Ts)[33] = (float(*)[33])pool;
        int idx = bx - 768;
        int z = idx >> 8, rem = idx & 255;
        const float* src = z ? Wo : Wv;
        __half* dst = z ? g_Woh : g_Wvh;
        int k0 = (rem >> 4) * 32, n0 = (rem & 15) * 32;
        int r = tid >> 3, c4 = (tid & 7) << 2;
        float4 w = *(const float4*)(src + (size_t)(k0 + r) * Dd + n0 + c4);
        Ts[r][c4 + 0] = w.x; Ts[r][c4 + 1] = w.y;
        Ts[r][c4 + 2] = w.z; Ts[r][c4 + 3] = w.w;
        __syncthreads();
        __half2 h0 = __floats2half2_rn(Ts[c4 + 0][r], Ts[c4 + 1][r]);
        __half2 h1 = __floats2half2_rn(Ts[c4 + 2][r], Ts[c4 + 3][r]);
        uint2 u; u.x = *(u32*)&h0; u.y = *(u32*)&h1;
        *(uint2*)(dst + (size_t)(n0 + r) * Dd + k0 + c4) = u;
    } else {
        float (*At)[68] = (float(*)[68])pool;
        float (*Wt)[65] = (float(*)[65])(pool + 64 * 68);
        int idx = bx - 1280;
        int sel = idx >> 6, h = (idx >> 3) & 7, R0 = (idx & 7) * 64;
        const float* W = sel ? Wk : Wq;
        const float* A = sel ? Ak : Aq;
        const float* bs = sel ? bki : bqi;
        __half* Wd = sel ? g_Wkh : g_Wqh;
        float* bd = sel ? g_bk : g_bq;

        {
            int j = tid >> 2, c0 = (tid & 3) << 4;
            #pragma unroll
            for (int i = 0; i < 4; i++) {
                float4 a = *(const float4*)(A + j * 64 + c0 + i * 4);
                At[j][c0 + i * 4 + 0] = a.x; At[j][c0 + i * 4 + 1] = a.y;
                At[j][c0 + i * 4 + 2] = a.z; At[j][c0 + i * 4 + 3] = a.w;
            }
            int r = tid >> 2, j0 = (tid & 3) << 4;
            #pragma unroll
            for (int i = 0; i < 4; i++) {
                float4 w = *(const float4*)(W + (size_t)(R0 + r) * Dd + h * 64 + j0 + i * 4);
                Wt[j0 + i * 4 + 0][r] = w.x; Wt[j0 + i * 4 + 1][r] = w.y;
                Wt[j0 + i * 4 + 2][r] = w.z; Wt[j0 + i * 4 + 3][r] = w.w;
            }
        }
        __syncthreads();

        int w = tid >> 5, l = tid & 31;
        int c0 = w * 8;
        float acc0[8] = {}, acc1[8] = {};
        #pragma unroll 8
        for (int j = 0; j < 64; j++) {
            float w0 = Wt[j][l], w1 = Wt[j][l + 32];
            float4 a0 = *(const float4*)&At[j][c0];
            float4 a1 = *(const float4*)&At[j][c0 + 4];
            acc0[0] += w0 * a0.x; acc0[1] += w0 * a0.y; acc0[2] += w0 * a0.z; acc0[3] += w0 * a0.w;
            acc0[4] += w0 * a1.x; acc0[5] += w0 * a1.y; acc0[6] += w0 * a1.z; acc0[7] += w0 * a1.w;
            acc1[0] += w1 * a0.x; acc1[1] += w1 * a0.y; acc1[2] += w1 * a0.z; acc1[3] += w1 * a0.w;
            acc1[4] += w1 * a1.x; acc1[5] += w1 * a1.y; acc1[6] += w1 * a1.z; acc1[7] += w1 * a1.w;
        }
        #pragma unroll
        for (int i = 0; i < 8; i++) {
            int c = c0 + i;
            Wd[(size_t)(h * 64 + c) * Dd + R0 + l]      = __float2half(acc0[i]);
            Wd[(size_t)(h * 64 + c) * Dd + R0 + 32 + l] = __float2half(acc1[i]);
        }

        if (R0 == 0 && tid < 64) {
            float bacc = 0.f;
            #pragma unroll 16
            for (int j = 0; j < 64; j++) bacc += bs[h * 64 + j] * At[j][tid];
            bd[h * 64 + tid] = bacc;
        }
    }
}

// ---------------- HMMA tile: 64m x 64n, K=512, 64-k chunks, 3-stage cp.async ----
template <int MODE>
__device__ __forceinline__ void mma_tile(const __half* __restrict__ X, int lda,
                                         const __half* __restrict__ BT, int ldb,
                                         const float* __restrict__ bias,
                                         __half* __restrict__ outh,
                                         float* __restrict__ outf,
                                         int m0, int n0, int ldo) {
    extern __shared__ __half mt_smem[];
    const u32 PLANE = 64 * 72 * 2;
    u32 abase = (u32)__cvta_generic_to_shared(mt_smem);
    u32 bbase = abase + 3 * PLANE;

    int tid = threadIdx.x, wid = tid >> 5, lane = tid & 31;
    int wm = (wid & 1) * 32, wn = (wid >> 1) * 16;
    int g = lane >> 2, qd = (lane & 3) * 2;
    int sr = tid >> 2, sk = (tid & 3) << 4;
    int lrow = lane & 15, lcol = (lane >> 4) << 3;

    float acc[2][2][4] = {};

    const __half* xg = X + (size_t)(m0 + sr) * lda + sk;
    const __half* bg = BT + (size_t)(n0 + sr) * ldb + sk;
    u32 adst = abase + (sr * 72 + sk) * 2;
    u32 bdst = bbase + (sr * 72 + sk) * 2;

#define STAGE_MT(p, k0) do { \
        cp16(adst + (u32)(p) * PLANE,      xg + (k0)); \
        cp16(adst + (u32)(p) * PLANE + 16, xg + (k0) + 8); \
        cp16(bdst + (u32)(p) * PLANE,      bg + (k0)); \
        cp16(bdst + (u32)(p) * PLANE + 16, bg + (k0) + 8); \
        asm volatile("cp.async.commit_group;"); } while (0)

    STAGE_MT(0, 0);
    STAGE_MT(1, 64);

    int buf = 0;
    for (int ch = 0; ch < 8; ch++) {
        if (ch < 7) asm volatile("cp.async.wait_group 1;");
        else        asm volatile("cp.async.wait_group 0;");
        __syncthreads();
        if (ch + 2 < 8) {
            int nb = buf + 2; if (nb >= 3) nb -= 3;
            STAGE_MT(nb, (ch + 2) * 64);
        }
        u32 abuf = abase + (u32)buf * PLANE;
        u32 bbuf = bbase + (u32)buf * PLANE;
        #pragma unroll
        for (int ks = 0; ks < 64; ks += 16) {
            u32 a[2][4], b[2][2];
            ldsm4(a[0][0], a[0][1], a[0][2], a[0][3],
                  abuf + ((wm + lrow) * 72 + ks + lcol) * 2);
            ldsm4(a[1][0], a[1][1], a[1][2], a[1][3],
                  abuf + ((wm + 16 + lrow) * 72 + ks + lcol) * 2);
            u32 r0, r1, r2, r3;
            ldsm4(r0, r1, r2, r3,
                  bbuf + ((wn + lrow) * 72 + ks + lcol) * 2);
            b[0][0] = r0; b[0][1] = r2; b[1][0] = r1; b[1][1] = r3;
            mma16816(acc[0][0], a[0], b[0]); mma16816(acc[0][1], a[0], b[1]);
            mma16816(acc[1][0], a[1], b[0]); mma16816(acc[1][1], a[1], b[1]);
        }
        if (++buf == 3) buf = 0;
    }
#undef STAGE_MT

    #pragma unroll
    for (int mm = 0; mm < 2; mm++) {
        #pragma unroll
        for (int nn = 0; nn < 2; nn++) {
            int M = m0 + wm + mm * 16;
            int N = n0 + wn + nn * 8 + qd;
            float b0 = bias ? bias[N] : 0.f;
            float b1 = bias ? bias[N + 1] : 0.f;
            float c0 = acc[mm][nn][0] + b0, c1 = acc[mm][nn][1] + b1;
            float c2 = acc[mm][nn][2] + b0, c3 = acc[mm][nn][3] + b1;
            if (MODE == 0) {
                __half2 h01 = __floats2half2_rn(c0, c1);
                __half2 h23 = __floats2half2_rn(c2, c3);
                *(u32*)(outh + (size_t)(M + g) * ldo + N)     = *(u32*)&h01;
                *(u32*)(outh + (size_t)(M + g + 8) * ldo + N) = *(u32*)&h23;
            } else if (MODE == 1) {
                int bb = M >> 9;
                int s = (M & 511) + g;
                int h = N >> 6, dd = N & 63;
                __half* r0 = outh + ((size_t)((bb * Hd + h) * HDd + dd)) * Sd;
                __half* r1 = r0 + Sd;
                r0[s] = __float2half(c0); r1[s] = __float2half(c1);
                r0[s + 8] = __float2half(c2); r1[s + 8] = __float2half(c3);
            } else {
                float2 o0 = { c0, c1 }, o1 = { c2, c3 };
                *(float2*)(outf + (size_t)(M + g) * ldo + N)     = o0;
                *(float2*)(outf + (size_t)(M + g + 8) * ldo + N) = o1;
            }
        }
    }
}

__global__ __launch_bounds__(256) void proj_mma_kernel(const float* __restrict__ bv) {
    int z = blockIdx.z;
    int m0 = blockIdx.y * 64, n0 = blockIdx.x * 64;
    if (z == 0)
        mma_tile<0>(g_xq16, Dd, g_Wqh, Dd, g_bq, g_qth, nullptr, m0, n0, Dd);
    else if (z == 1)
        mma_tile<0>(g_xk16, Dd, g_Wkh, Dd, g_bk, g_kth, nullptr, m0, n0, Dd);
    else
        mma_tile<1>(g_xv16, Dd, g_Wvh, Dd, bv, g_v16T, nullptr, m0, n0, 0);
}

__global__ __launch_bounds__(256) void out_mma_kernel(const float* __restrict__ bo,
                                                      float* __restrict__ out) {
    mma_tile<2>(g_ctx16, Dd, g_Woh, Dd, bo, nullptr, out,
                blockIdx.y * 64, blockIdx.x * 64, Dd);
}

// ---------------- scores + softmax + fused ctx, 8 q-rows/block ----------
// 256 thr = 8 warps = 8 q rows; 1024 blocks. qq/aa hoisted to registers
// (chunk-invariant); f16 accumulator chains split 2+2 for ILP 4.
#define SC_QS   16384
#define SC_AVH  17408
#define SC_ATT  17536
#define SC_VB   34176
#define SC_VBS  17408
#define SC_SMEM 68992

__global__ __launch_bounds__(256, 2) void scores_kernel(const float* __restrict__ av,
                                                        float* __restrict__ attn_out) {
    extern __shared__ char smpool[];
    uint4 (*qs4)[8] = (uint4(*)[8])(smpool + SC_QS);
    uint4 *avh4     = (uint4*)(smpool + SC_AVH);
    __half (*att)[520] = (__half(*)[520])(smpool + SC_ATT);

    int b = blockIdx.z, h = blockIdx.y;
    int q0 = blockIdx.x * 8;
    int tid = threadIdx.x;
    int w = tid >> 5, ln = tid & 31;
    int swl = ln & 7;
    int g = ln >> 2, qd = (ln & 3) * 2;

    u32 ksbase = (u32)__cvta_generic_to_shared(smpool);
    u32 vbase  = ksbase + SC_VB;
    const __half* ksrc = g_kth + ((size_t)(b * Sd)) * Dd + h * HDd;
    const __half* vsrc = g_v16T + ((size_t)((b * Hd + h) * HDd)) * Sd;

    // stage k chunk 0 (async, swizzled)
    {
        #pragma unroll
        for (int i = 0; i < 2; i++) {
            int t = tid + i * 256;
            int row = t >> 3, c4 = t & 7;
            cp16(ksbase + (((row << 3) + (c4 ^ (row & 7))) << 4),
                 ksrc + (size_t)row * Dd + c4 * 8);
        }
        asm volatile("cp.async.commit_group;");
    }
    if (tid < 64) {
        int row = tid >> 3, c4 = tid & 7;
        qs4[row][c4] =
            *(const uint4*)(g_qth + ((size_t)(b * Sd + q0 + row)) * Dd + h * HDd + c4 * 8);
    } else if (tid < 96) {
        int i = tid - 64;
        __half2 hh = __floats2half2_rn(av[2 * i], av[2 * i + 1]);
        ((u32*)avh4)[i] = *(u32*)&hh;
    }
    __syncthreads();

    // hoist q-row + av into registers (chunk-invariant)
    uint4 qq[8], aa[8];
    #pragma unroll
    for (int j = 0; j < 8; j++) { qq[j] = qs4[w][j]; aa[j] = avh4[j]; }

    float s[8][2];

    for (int ch = 0; ch < 8; ch++) {
        asm volatile("cp.async.wait_group 0;");
        __syncthreads();
        if (ch < 7) {   // stage k chunk ch+1; at ch==6 also prefetch v tile kc=0
            u32 kb = ksbase + (u32)((ch + 1) & 1) * 8192;
            const __half* src = ksrc + (size_t)(ch + 1) * 64 * Dd;
            #pragma unroll
            for (int i = 0; i < 2; i++) {
                int t = tid + i * 256;
                int row = t >> 3, c4 = t & 7;
                cp16(kb + (((row << 3) + (c4 ^ (row & 7))) << 4),
                     src + (size_t)row * Dd + c4 * 8);
            }
            if (ch == 6) {
                #pragma unroll
                for (int i = 0; i < 4; i++) {
                    int t = tid + i * 256;
                    int dRow = t >> 4, cs = (t & 15) * 8;
                    cp16(vbase + (dRow * 136 + cs) * 2,
                         vsrc + (size_t)dRow * Sd + cs);
                }
            }
            asm volatile("cp.async.commit_group;");
        }

        uint4 (*ks4)[8] = (uint4(*)[8])(smpool + (u32)(ch & 1) * 8192);
        float sa0 = 0.f, sa1 = 0.f;
        #pragma unroll
        for (int j = 0; j < 8; j++) {
            int sc = j ^ swl;
            uint4 k0 = ks4[ln][sc];
            uint4 k1 = ks4[32 + ln][sc];
            // 4 independent chains of length 2 (ILP 4)
            u32 a0x = 0, a0y = 0, a1x = 0, a1y = 0;
            tchain(qq[j].x, k0.x, aa[j].x, a0x);
            tchain(qq[j].y, k0.y, aa[j].y, a0y);
            tchain(qq[j].x, k1.x, aa[j].x, a1x);
            tchain(qq[j].y, k1.y, aa[j].y, a1y);
            tchain(qq[j].z, k0.z, aa[j].z, a0x);
            tchain(qq[j].w, k0.w, aa[j].w, a0y);
            tchain(qq[j].z, k1.z, aa[j].z, a1x);
            tchain(qq[j].w, k1.w, aa[j].w, a1y);
            u32 m0 = hadd2u(a0x, a0y);
            u32 m1 = hadd2u(a1x, a1y);
            float lo, hi;
            h2f2(m0, lo, hi); sa0 += lo + hi;
            h2f2(m1, lo, hi); sa1 += lo + hi;
        }
        s[ch][0] = sa0; s[ch][1] = sa1;
    }

    // softmax (registers + shuffles only); k = ch*64 + m*32 + ln
    float mx = -1e30f;
    #pragma unroll
    for (int ch = 0; ch < 8; ch++) {
        mx = fmaxf(mx, s[ch][0]);
        mx = fmaxf(mx, s[ch][1]);
    }
    #pragma unroll
    for (int o = 16; o > 0; o >>= 1) mx = fmaxf(mx, __shfl_xor_sync(0xffffffffu, mx, o));
    float sum = 0.f;
    #pragma unroll
    for (int ch = 0; ch < 8; ch++) {
        s[ch][0] = __expf(s[ch][0] - mx); sum += s[ch][0];
        s[ch][1] = __expf(s[ch][1] - mx); sum += s[ch][1];
    }
    #pragma unroll
    for (int o = 16; o > 0; o >>= 1) sum += __shfl_xor_sync(0xffffffffu, sum, o);
    float inv = 1.f / sum;

    // write attn: fp32 -> gmem (required output), f16 -> smem tile (own row)
    size_t rowoff = (((size_t)(b * Hd + h) * Sd) + q0 + w) * Sd;
    float* arow = attn_out + rowoff;
    #pragma unroll
    for (int ch = 0; ch < 8; ch++)
        #pragma unroll
        for (int m = 0; m < 2; m++) {
            float a = s[ch][m] * inv;
            int kk = ch * 64 + m * 32 + ln;
            arow[kk] = a;
            att[w][kk] = __float2half(a);
        }

    // -------- fused ctx: ctx[8 q][64 d] = att[8][512] @ v[512][64] --------
    int wn = w * 8;
    float cacc[4] = {0.f, 0.f, 0.f, 0.f};

    for (int kc = 0; kc < 4; kc++) {
        asm volatile("cp.async.wait_group 0;");
        __syncthreads();
        if (kc < 3) {
            u32 vb = vbase + (u32)((kc + 1) & 1) * SC_VBS;
            const __half* src = vsrc + (size_t)(kc + 1) * 128;
            #pragma unroll
            for (int i = 0; i < 4; i++) {
                int t = tid + i * 256;
                int dRow = t >> 4, cs = (t & 15) * 8;
                cp16(vb + (dRow * 136 + cs) * 2, src + (size_t)dRow * Sd + cs);
            }
            asm volatile("cp.async.commit_group;");
        }
        {
            __half (*vbuf)[136] = (__half(*)[136])(smpool + SC_VB + (u32)(kc & 1) * SC_VBS);
            #pragma unroll
            for (int ks = 0; ks < 8; ks++) {
                int kcol = kc * 128 + ks * 16;
                u32 a[4], bf[2];
                a[0] = *(const u32*)&att[g][kcol + qd];
                a[1] = *(const u32*)&att[g + 8][kcol + qd];       // don't-care rows
                a[2] = *(const u32*)&att[g][kcol + qd + 8];
                a[3] = *(const u32*)&att[g + 8][kcol + qd + 8];   // don't-care rows
                bf[0] = *(const u32*)&vbuf[wn + g][ks * 16 + qd];
                bf[1] = *(const u32*)&vbuf[wn + g][ks * 16 + qd + 8];
                mma16816(cacc, a, bf);
            }
        }
    }

    {
        int dcol = h * 64 + wn + qd;
        __half2 h01 = __floats2half2_rn(cacc[0], cacc[1]);
        *(u32*)(g_ctx16 + (size_t)(b * Sd + q0 + g) * Dd + dcol) = *(u32*)&h01;
    }
}

// ---------------- launch ----------------
#define MT_SMEM 55296

extern "C" void kernel_launch(void* const* d_in, const int* in_sizes, int n_in,
                              void* d_out, int out_size) {
    const float* query = (const float*)d_in[0];
    const float* key_  = (const float*)d_in[1];
    const float* value = (const float*)d_in[2];
    const float* Wq    = (const float*)d_in[3];
    const float* bq    = (const float*)d_in[4];
    const float* Wk    = (const float*)d_in[5];
    const float* bk    = (const float*)d_in[6];
    const float* Wv    = (const float*)d_in[7];
    const float* bv    = (const float*)d_in[8];
    const float* Wo    = (const float*)d_in[9];
    const float* bo    = (const float*)d_in[10];
    const float* Aq    = (const float*)d_in[11];
    const float* Ak    = (const float*)d_in[12];
    const float* av    = (const float*)d_in[13];

    float* out      = (float*)d_out;                  // [B,S,D]
    float* attn_out = out + (size_t)Bd * Sd * Dd;     // [B,H,S,S]

    cudaFuncSetAttribute(proj_mma_kernel, cudaFuncAttributeMaxDynamicSharedMemorySize, MT_SMEM);
    cudaFuncSetAttribute(out_mma_kernel,  cudaFuncAttributeMaxDynamicSharedMemorySize, MT_SMEM);
    cudaFuncSetAttribute(scores_kernel,   cudaFuncAttributeMaxDynamicSharedMemorySize, SC_SMEM);

    prep_fold_kernel<<<1408, 256>>>(query, key_, value, Wv, Wo,
                                    Wq, Aq, bq, Wk, Ak, bk);
    proj_mma_kernel<<<dim3(8, 16, 3), 256, MT_SMEM>>>(bv);
    scores_kernel<<<dim3(64, Hd, Bd), 256, SC_SMEM>>>(av, attn_out);
    out_mma_kernel<<<dim3(8, 16), 256, MT_SMEM>>>(bo, out);
}

// round 17
// speedup vs baseline: 1.0274x; 1.0274x over previous
#include <cuda_runtime.h>
#include <cuda_fp16.h>

#define Dd  512
#define Sd  512
#define Bd  2
#define Hd  8
#define HDd 64

typedef unsigned long long u64;
typedef unsigned int u32;

// ---------------- scratch (device globals) ----------------
__device__ __half g_Wqh[Dd * Dd];       // folded Wq@Aq, transposed [n][k], f16
__device__ __half g_Wkh[Dd * Dd];       // folded Wk@Ak, transposed [n][k], f16
__device__ __half g_Wvh[Dd * Dd];       // Wv transposed [n][k], f16
__device__ __half g_Woh[Dd * Dd];       // Wo transposed [n][k], f16
__device__ float  g_bq[Dd];
__device__ float  g_bk[Dd];
__device__ __half g_xq16[Bd * Sd * Dd];
__device__ __half g_xk16[Bd * Sd * Dd];
__device__ __half g_xv16[Bd * Sd * Dd];
__device__ __half g_qth[Bd * Sd * Dd];  // q_term f16, row-major
__device__ __half g_kth[Bd * Sd * Dd];  // k_term f16
__device__ __half g_v16T[Bd * Hd * HDd * Sd]; // v, per (b,h) transposed [d][s]
__device__ __half g_ctx16[Bd * Sd * Dd];      // ctx f16, row-major

// ---------------- asm helpers ----------------
__device__ __forceinline__ void h2f2(u32 h, float& lo, float& hi) {
    asm("{ .reg .b16 l, h;\n\t mov.b32 {l, h}, %2;\n\t"
        " cvt.f32.f16 %0, l;\n\t cvt.f32.f16 %1, h; }"
        : "=f"(lo), "=f"(hi) : "r"(h));
}
__device__ __forceinline__ void tchain(u32 q2, u32 k2, u32 a2, u32& acch) {
    u32 x2, t2;
    asm("add.rn.f16x2 %0, %1, %2;" : "=r"(x2) : "r"(q2), "r"(k2));
    asm("tanh.approx.f16x2 %0, %1;" : "=r"(t2) : "r"(x2));
    asm("fma.rn.f16x2 %0, %1, %2, %0;" : "+r"(acch) : "r"(t2), "r"(a2));
}
__device__ __forceinline__ void mma16816(float* d, const u32* a, const u32* b) {
    asm volatile(
        "mma.sync.aligned.m16n8k16.row.col.f32.f16.f16.f32 "
        "{%0,%1,%2,%3}, {%4,%5,%6,%7}, {%8,%9}, {%0,%1,%2,%3};"
        : "+f"(d[0]), "+f"(d[1]), "+f"(d[2]), "+f"(d[3])
        : "r"(a[0]), "r"(a[1]), "r"(a[2]), "r"(a[3]), "r"(b[0]), "r"(b[1]));
}
__device__ __forceinline__ void ldsm4(u32& r0, u32& r1, u32& r2, u32& r3, u32 addr) {
    asm volatile("ldmatrix.sync.aligned.m8n8.x4.shared.b16 {%0,%1,%2,%3}, [%4];"
                 : "=r"(r0), "=r"(r1), "=r"(r2), "=r"(r3) : "r"(addr));
}
__device__ __forceinline__ void cp16(u32 dst, const void* src) {
    asm volatile("cp.async.cg.shared.global [%0], [%1], 16;" :: "r"(dst), "l"(src));
}

// ---------------- fused prep + fold (unchanged) ----------------
__global__ __launch_bounds__(256) void prep_fold_kernel(
        const float* __restrict__ q, const float* __restrict__ k,
        const float* __restrict__ v,
        const float* __restrict__ Wv, const float* __restrict__ Wo,
        const float* __restrict__ Wq, const float* __restrict__ Aq,
        const float* __restrict__ bqi,
        const float* __restrict__ Wk, const float* __restrict__ Ak,
        const float* __restrict__ bki) {
    __shared__ float pool[8512];
    int bx = blockIdx.x, tid = threadIdx.x;

    if (bx < 768) {
        int t = bx * 256 + tid;
        int sel = t >> 16;
        const float* src = (sel == 0) ? q : (sel == 1) ? k : v;
        __half* dst = (sel == 0) ? g_xq16 : (sel == 1) ? g_xk16 : g_xv16;
        int base = (t & 65535) * 8;
        float4 a = *(const float4*)(src + base);
        float4 b = *(const float4*)(src + base + 4);
        __half2 h0 = __floats2half2_rn(a.x, a.y), h1 = __floats2half2_rn(a.z, a.w);
        __half2 h2 = __floats2half2_rn(b.x, b.y), h3 = __floats2half2_rn(b.z, b.w);
        uint4 u;
        u.x = *(u32*)&h0; u.y = *(u32*)&h1; u.z = *(u32*)&h2; u.w = *(u32*)&h3;
        *(uint4*)(dst + base) = u;
    } else if (bx < 1280) {
        float (*Ts)[33] = (float(*)[33])pool;
        int idx = bx - 768;
        int z = idx >> 8, rem = idx & 255;
        const float* src = z ? Wo : Wv;
        __half* dst = z ? g_Woh : g_Wvh;
        int k0 = (rem >> 4) * 32, n0 = (rem & 15) * 32;
        int r = tid >> 3, c4 = (tid & 7) << 2;
        float4 w = *(const float4*)(src + (size_t)(k0 + r) * Dd + n0 + c4);
        Ts[r][c4 + 0] = w.x; Ts[r][c4 + 1] = w.y;
        Ts[r][c4 + 2] = w.z; Ts[r][c4 + 3] = w.w;
        __syncthreads();
        __half2 h0 = __floats2half2_rn(Ts[c4 + 0][r], Ts[c4 + 1][r]);
        __half2 h1 = __floats2half2_rn(Ts[c4 + 2][r], Ts[c4 + 3][r]);
        uint2 u; u.x = *(u32*)&h0; u.y = *(u32*)&h1;
        *(uint2*)(dst + (size_t)(n0 + r) * Dd + k0 + c4) = u;
    } else {
        float (*At)[68] = (float(*)[68])pool;
        float (*Wt)[65] = (float(*)[65])(pool + 64 * 68);
        int idx = bx - 1280;
        int sel = idx >> 6, h = (idx >> 3) & 7, R0 = (idx & 7) * 64;
        const float* W = sel ? Wk : Wq;
        const float* A = sel ? Ak : Aq;
        const float* bs = sel ? bki : bqi;
        __half* Wd = sel ? g_Wkh : g_Wqh;
        float* bd = sel ? g_bk : g_bq;

        {
            int j = tid >> 2, c0 = (tid & 3) << 4;
            #pragma unroll
            for (int i = 0; i < 4; i++) {
                float4 a = *(const float4*)(A + j * 64 + c0 + i * 4);
                At[j][c0 + i * 4 + 0] = a.x; At[j][c0 + i * 4 + 1] = a.y;
                At[j][c0 + i * 4 + 2] = a.z; At[j][c0 + i * 4 + 3] = a.w;
            }
            int r = tid >> 2, j0 = (tid & 3) << 4;
            #pragma unroll
            for (int i = 0; i < 4; i++) {
                float4 w = *(const float4*)(W + (size_t)(R0 + r) * Dd + h * 64 + j0 + i * 4);
                Wt[j0 + i * 4 + 0][r] = w.x; Wt[j0 + i * 4 + 1][r] = w.y;
                Wt[j0 + i * 4 + 2][r] = w.z; Wt[j0 + i * 4 + 3][r] = w.w;
            }
        }
        __syncthreads();

        int w = tid >> 5, l = tid & 31;
        int c0 = w * 8;
        float acc0[8] = {}, acc1[8] = {};
        #pragma unroll 8
        for (int j = 0; j < 64; j++) {
            float w0 = Wt[j][l], w1 = Wt[j][l + 32];
            float4 a0 = *(const float4*)&At[j][c0];
            float4 a1 = *(const float4*)&At[j][c0 + 4];
            acc0[0] += w0 * a0.x; acc0[1] += w0 * a0.y; acc0[2] += w0 * a0.z; acc0[3] += w0 * a0.w;
            acc0[4] += w0 * a1.x; acc0[5] += w0 * a1.y; acc0[6] += w0 * a1.z; acc0[7] += w0 * a1.w;
            acc1[0] += w1 * a0.x; acc1[1] += w1 * a0.y; acc1[2] += w1 * a0.z; acc1[3] += w1 * a0.w;
            acc1[4] += w1 * a1.x; acc1[5] += w1 * a1.y; acc1[6] += w1 * a1.z; acc1[7] += w1 * a1.w;
        }
        #pragma unroll
        for (int i = 0; i < 8; i++) {
            int c = c0 + i;
            Wd[(size_t)(h * 64 + c) * Dd + R0 + l]      = __float2half(acc0[i]);
            Wd[(size_t)(h * 64 + c) * Dd + R0 + 32 + l] = __float2half(acc1[i]);
        }

        if (R0 == 0 && tid < 64) {
            float bacc = 0.f;
            #pragma unroll 16
            for (int j = 0; j < 64; j++) bacc += bs[h * 64 + j] * At[j][tid];
            bd[h * 64 + tid] = bacc;
        }
    }
}

// ---------------- HMMA tile: 64m x 64n, K=512, 64-k chunks, 3-stage cp.async ----
template <int MODE>
__device__ __forceinline__ void mma_tile(const __half* __restrict__ X, int lda,
                                         const __half* __restrict__ BT, int ldb,
                                         const float* __restrict__ bias,
                                         __half* __restrict__ outh,
                                         float* __restrict__ outf,
                                         int m0, int n0, int ldo) {
    extern __shared__ __half mt_smem[];
    const u32 PLANE = 64 * 72 * 2;
    u32 abase = (u32)__cvta_generic_to_shared(mt_smem);
    u32 bbase = abase + 3 * PLANE;

    int tid = threadIdx.x, wid = tid >> 5, lane = tid & 31;
    int wm = (wid & 1) * 32, wn = (wid >> 1) * 16;
    int g = lane >> 2, qd = (lane & 3) * 2;
    int sr = tid >> 2, sk = (tid & 3) << 4;
    int lrow = lane & 15, lcol = (lane >> 4) << 3;

    float acc[2][2][4] = {};

    const __half* xg = X + (size_t)(m0 + sr) * lda + sk;
    const __half* bg = BT + (size_t)(n0 + sr) * ldb + sk;
    u32 adst = abase + (sr * 72 + sk) * 2;
    u32 bdst = bbase + (sr * 72 + sk) * 2;

#define STAGE_MT(p, k0) do { \
        cp16(adst + (u32)(p) * PLANE,      xg + (k0)); \
        cp16(adst + (u32)(p) * PLANE + 16, xg + (k0) + 8); \
        cp16(bdst + (u32)(p) * PLANE,      bg + (k0)); \
        cp16(bdst + (u32)(p) * PLANE + 16, bg + (k0) + 8); \
        asm volatile("cp.async.commit_group;"); } while (0)

    STAGE_MT(0, 0);
    STAGE_MT(1, 64);

    int buf = 0;
    for (int ch = 0; ch < 8; ch++) {
        if (ch < 7) asm volatile("cp.async.wait_group 1;");
        else        asm volatile("cp.async.wait_group 0;");
        __syncthreads();
        if (ch + 2 < 8) {
            int nb = buf + 2; if (nb >= 3) nb -= 3;
            STAGE_MT(nb, (ch + 2) * 64);
        }
        u32 abuf = abase + (u32)buf * PLANE;
        u32 bbuf = bbase + (u32)buf * PLANE;
        #pragma unroll
        for (int ks = 0; ks < 64; ks += 16) {
            u32 a[2][4], b[2][2];
            ldsm4(a[0][0], a[0][1], a[0][2], a[0][3],
                  abuf + ((wm + lrow) * 72 + ks + lcol) * 2);
            ldsm4(a[1][0], a[1][1], a[1][2], a[1][3],
                  abuf + ((wm + 16 + lrow) * 72 + ks + lcol) * 2);
            u32 r0, r1, r2, r3;
            ldsm4(r0, r1, r2, r3,
                  bbuf + ((wn + lrow) * 72 + ks + lcol) * 2);
            b[0][0] = r0; b[0][1] = r2; b[1][0] = r1; b[1][1] = r3;
            mma16816(acc[0][0], a[0], b[0]); mma16816(acc[0][1], a[0], b[1]);
            mma16816(acc[1][0], a[1], b[0]); mma16816(acc[1][1], a[1], b[1]);
        }
        if (++buf == 3) buf = 0;
    }
#undef STAGE_MT

    #pragma unroll
    for (int mm = 0; mm < 2; mm++) {
        #pragma unroll
        for (int nn = 0; nn < 2; nn++) {
            int M = m0 + wm + mm * 16;
            int N = n0 + wn + nn * 8 + qd;
            float b0 = bias ? bias[N] : 0.f;
            float b1 = bias ? bias[N + 1] : 0.f;
            float c0 = acc[mm][nn][0] + b0, c1 = acc[mm][nn][1] + b1;
            float c2 = acc[mm][nn][2] + b0, c3 = acc[mm][nn][3] + b1;
            if (MODE == 0) {
                __half2 h01 = __floats2half2_rn(c0, c1);
                __half2 h23 = __floats2half2_rn(c2, c3);
                *(u32*)(outh + (size_t)(M + g) * ldo + N)     = *(u32*)&h01;
                *(u32*)(outh + (size_t)(M + g + 8) * ldo + N) = *(u32*)&h23;
            } else if (MODE == 1) {
                int bb = M >> 9;
                int s = (M & 511) + g;
                int h = N >> 6, dd = N & 63;
                __half* r0 = outh + ((size_t)((bb * Hd + h) * HDd + dd)) * Sd;
                __half* r1 = r0 + Sd;
                r0[s] = __float2half(c0); r1[s] = __float2half(c1);
                r0[s + 8] = __float2half(c2); r1[s + 8] = __float2half(c3);
            } else {
                float2 o0 = { c0, c1 }, o1 = { c2, c3 };
                *(float2*)(outf + (size_t)(M + g) * ldo + N)     = o0;
                *(float2*)(outf + (size_t)(M + g + 8) * ldo + N) = o1;
            }
        }
    }
}

__global__ __launch_bounds__(256) void proj_mma_kernel(const float* __restrict__ bv) {
    int z = blockIdx.z;
    int m0 = blockIdx.y * 64, n0 = blockIdx.x * 64;
    if (z == 0)
        mma_tile<0>(g_xq16, Dd, g_Wqh, Dd, g_bq, g_qth, nullptr, m0, n0, Dd);
    else if (z == 1)
        mma_tile<0>(g_xk16, Dd, g_Wkh, Dd, g_bk, g_kth, nullptr, m0, n0, Dd);
    else
        mma_tile<1>(g_xv16, Dd, g_Wvh, Dd, bv, g_v16T, nullptr, m0, n0, 0);
}

__global__ __launch_bounds__(256) void out_mma_kernel(const float* __restrict__ bo,
                                                      float* __restrict__ out) {
    mma_tile<2>(g_ctx16, Dd, g_Woh, Dd, bo, nullptr, out,
                blockIdx.y * 64, blockIdx.x * 64, Dd);
}

// ---------------- scores + softmax + fused ctx, 8 q-rows/block, 3 CTAs/SM ----
// R14 base; ctx v-pipeline re-scheduled: kc1 staged under softmax shadow,
// kc2/kc3 staged 2-rounds ahead (wait_group 1). Accumulation order unchanged.
#define SC_QS   16384
#define SC_AVH  17408
#define SC_ATT  17536
#define SC_VB   34176
#define SC_VBS  17408
#define SC_SMEM 68992

__global__ __launch_bounds__(256, 3) void scores_kernel(const float* __restrict__ av,
                                                        float* __restrict__ attn_out) {
    extern __shared__ char smpool[];
    uint4 (*qs4)[8] = (uint4(*)[8])(smpool + SC_QS);
    uint4 *avh4     = (uint4*)(smpool + SC_AVH);
    __half (*att)[520] = (__half(*)[520])(smpool + SC_ATT);

    int b = blockIdx.z, h = blockIdx.y;
    int q0 = blockIdx.x * 8;
    int tid = threadIdx.x;
    int w = tid >> 5, ln = tid & 31;
    int swl = ln & 7;
    int g = ln >> 2, qd = (ln & 3) * 2;

    u32 ksbase = (u32)__cvta_generic_to_shared(smpool);
    u32 vbase  = ksbase + SC_VB;
    const __half* ksrc = g_kth + ((size_t)(b * Sd)) * Dd + h * HDd;
    const __half* vsrc = g_v16T + ((size_t)((b * Hd + h) * HDd)) * Sd;

    // stage k chunk 0 (async, swizzled)
    {
        #pragma unroll
        for (int i = 0; i < 2; i++) {
            int t = tid + i * 256;
            int row = t >> 3, c4 = t & 7;
            cp16(ksbase + (((row << 3) + (c4 ^ (row & 7))) << 4),
                 ksrc + (size_t)row * Dd + c4 * 8);
        }
        asm volatile("cp.async.commit_group;");
    }
    if (tid < 64) {
        int row = tid >> 3, c4 = tid & 7;
        qs4[row][c4] =
            *(const uint4*)(g_qth + ((size_t)(b * Sd + q0 + row)) * Dd + h * HDd + c4 * 8);
    } else if (tid < 96) {
        int i = tid - 64;
        __half2 hh = __floats2half2_rn(av[2 * i], av[2 * i + 1]);
        ((u32*)avh4)[i] = *(u32*)&hh;
    }

    float s[8][2];

    for (int ch = 0; ch < 8; ch++) {
        asm volatile("cp.async.wait_group 0;");
        __syncthreads();
        if (ch < 7) {   // stage k chunk ch+1; at ch==6 also prefetch v tile kc=0
            u32 kb = ksbase + (u32)((ch + 1) & 1) * 8192;
            const __half* src = ksrc + (size_t)(ch + 1) * 64 * Dd;
            #pragma unroll
            for (int i = 0; i < 2; i++) {
                int t = tid + i * 256;
                int row = t >> 3, c4 = t & 7;
                cp16(kb + (((row << 3) + (c4 ^ (row & 7))) << 4),
                     src + (size_t)row * Dd + c4 * 8);
            }
            if (ch == 6) {
                #pragma unroll
                for (int i = 0; i < 4; i++) {
                    int t = tid + i * 256;
                    int dRow = t >> 4, cs = (t & 15) * 8;
                    cp16(vbase + (dRow * 136 + cs) * 2,
                         vsrc + (size_t)dRow * Sd + cs);
                }
            }
            asm volatile("cp.async.commit_group;");
        }

        uint4 (*ks4)[8] = (uint4(*)[8])(smpool + (u32)(ch & 1) * 8192);
        float sa0 = 0.f, sa1 = 0.f;
        #pragma unroll
        for (int j = 0; j < 8; j++) {
            uint4 qq = qs4[w][j];
            uint4 aa = avh4[j];
            int sc = j ^ swl;
            uint4 k0 = ks4[ln][sc];
            uint4 k1 = ks4[32 + ln][sc];
            u32 a0 = 0, a1 = 0;
            tchain(qq.x, k0.x, aa.x, a0); tchain(qq.y, k0.y, aa.y, a0);
            tchain(qq.z, k0.z, aa.z, a0); tchain(qq.w, k0.w, aa.w, a0);
            tchain(qq.x, k1.x, aa.x, a1); tchain(qq.y, k1.y, aa.y, a1);
            tchain(qq.z, k1.z, aa.z, a1); tchain(qq.w, k1.w, aa.w, a1);
            float lo, hi;
            h2f2(a0, lo, hi); sa0 += lo + hi;
            h2f2(a1, lo, hi); sa1 += lo + hi;
        }
        s[ch][0] = sa0; s[ch][1] = sa1;
    }
    // all cp.async groups drained here (last wait_group 0 at ch==7);
    // v tile kc0 already resident in vbuf0.

    // stage v tile kc1 -> vbuf1 NOW; it lands under the softmax/epilogue shadow.
    {
        const __half* src = vsrc + 128;
        #pragma unroll
        for (int i = 0; i < 4; i++) {
            int t = tid + i * 256;
            int dRow = t >> 4, cs = (t & 15) * 8;
            cp16(vbase + SC_VBS + (dRow * 136 + cs) * 2, src + (size_t)dRow * Sd + cs);
        }
        asm volatile("cp.async.commit_group;");   // group G1
    }

    // softmax (registers + shuffles only); k = ch*64 + m*32 + ln
    float mx = -1e30f;
    #pragma unroll
    for (int ch = 0; ch < 8; ch++) {
        mx = fmaxf(mx, s[ch][0]);
        mx = fmaxf(mx, s[ch][1]);
    }
    #pragma unroll
    for (int o = 16; o > 0; o >>= 1) mx = fmaxf(mx, __shfl_xor_sync(0xffffffffu, mx, o));
    float sum = 0.f;
    #pragma unroll
    for (int ch = 0; ch < 8; ch++) {
        s[ch][0] = __expf(s[ch][0] - mx); sum += s[ch][0];
        s[ch][1] = __expf(s[ch][1] - mx); sum += s[ch][1];
    }
    #pragma unroll
    for (int o = 16; o > 0; o >>= 1) sum += __shfl_xor_sync(0xffffffffu, sum, o);
    float inv = 1.f / sum;

    // write attn: fp32 -> gmem (required output), f16 -> smem tile (own row)
    size_t rowoff = (((size_t)(b * Hd + h) * Sd) + q0 + w) * Sd;
    float* arow = attn_out + rowoff;
    #pragma unroll
    for (int ch = 0; ch < 8; ch++)
        #pragma unroll
        for (int m = 0; m < 2; m++) {
            float a = s[ch][m] * inv;
            int kk = ch * 64 + m * 32 + ln;
            arow[kk] = a;
            att[w][kk] = __float2half(a);
        }

    // -------- fused ctx: ctx[8 q][64 d] = att[8][512] @ v[512][64] --------
    // kc0 resident, kc1 in flight (G1). Stage kc2/kc3 two rounds ahead.
    // Accumulation order kc0->1->2->3 with identical per-round mma sequence.
    int wn = w * 8;
    float cacc[4] = {0.f, 0.f, 0.f, 0.f};

#define CTX_MMA(KC, VOFF) do { \
        __half (*vbuf)[136] = (__half(*)[136])(smpool + SC_VB + (u32)(VOFF)); \
        _Pragma("unroll") \
        for (int ks = 0; ks < 8; ks++) { \
            int kcol = (KC) * 128 + ks * 16; \
            u32 a[4], bf[2]; \
            a[0] = *(const u32*)&att[g][kcol + qd]; \
            a[1] = *(const u32*)&att[g + 8][kcol + qd]; \
            a[2] = *(const u32*)&att[g][kcol + qd + 8]; \
            a[3] = *(const u32*)&att[g + 8][kcol + qd + 8]; \
            bf[0] = *(const u32*)&vbuf[wn + g][ks * 16 + qd]; \
            bf[1] = *(const u32*)&vbuf[wn + g][ks * 16 + qd + 8]; \
            mma16816(cacc, a, bf); \
        } } while (0)

#define CTX_STAGE(KC, VOFF) do { \
        const __half* src = vsrc + (size_t)(KC) * 128; \
        _Pragma("unroll") \
        for (int i = 0; i < 4; i++) { \
            int t = tid + i * 256; \
            int dRow = t >> 4, cs = (t & 15) * 8; \
            cp16(vbase + (u32)(VOFF) + (dRow * 136 + cs) * 2, \
                 src + (size_t)dRow * Sd + cs); \
        } \
        asm volatile("cp.async.commit_group;"); } while (0)

    // kc0: data resident; barrier makes att visible to all warps.
    __syncthreads();
    CTX_MMA(0, 0);
    __syncthreads();              // vbuf0 reads done
    CTX_STAGE(2, 0);              // G2: kc2 -> vbuf0

    // kc1: G1 must be done (G2 may pend)
    asm volatile("cp.async.wait_group 1;");
    __syncthreads();
    CTX_MMA(1, SC_VBS);
    __syncthreads();              // vbuf1 reads done
    CTX_STAGE(3, SC_VBS);         // G3: kc3 -> vbuf1

    // kc2: G2 done (G3 may pend)
    asm volatile("cp.async.wait_group 1;");
    __syncthreads();
    CTX_MMA(2, 0);

    // kc3: everything done
    asm volatile("cp.async.wait_group 0;");
    __syncthreads();
    CTX_MMA(3, SC_VBS);

#undef CTX_MMA
#undef CTX_STAGE

    {
        int dcol = h * 64 + wn + qd;
        __half2 h01 = __floats2half2_rn(cacc[0], cacc[1]);
        *(u32*)(g_ctx16 + (size_t)(b * Sd + q0 + g) * Dd + dcol) = *(u32*)&h01;
    }
}

// ---------------- launch ----------------
#define MT_SMEM 55296

extern "C" void kernel_launch(void* const* d_in, const int* in_sizes, int n_in,
                              void* d_out, int out_size) {
    const float* query = (const float*)d_in[0];
    const float* key_  = (const float*)d_in[1];
    const float* value = (const float*)d_in[2];
    const float* Wq    = (const float*)d_in[3];
    const float* bq    = (const float*)d_in[4];
    const float* Wk    = (const float*)d_in[5];
    const float* bk    = (const float*)d_in[6];
    const float* Wv    = (const float*)d_in[7];
    const float* bv    = (const float*)d_in[8];
    const float* Wo    = (const float*)d_in[9];
    const float* bo    = (const float*)d_in[10];
    const float* Aq    = (const float*)d_in[11];
    const float* Ak    = (const float*)d_in[12];
    const float* av    = (const float*)d_in[13];

    float* out      = (float*)d_out;                  // [B,S,D]
    float* attn_out = out + (size_t)Bd * Sd * Dd;     // [B,H,S,S]

    cudaFuncSetAttribute(proj_mma_kernel, cudaFuncAttributeMaxDynamicSharedMemorySize, MT_SMEM);
    cudaFuncSetAttribute(out_mma_kernel,  cudaFuncAttributeMaxDynamicSharedMemorySize, MT_SMEM);
    cudaFuncSetAttribute(scores_kernel,   cudaFuncAttributeMaxDynamicSharedMemorySize, SC_SMEM);

    prep_fold_kernel<<<1408, 256>>>(query, key_, value, Wv, Wo,
                                    Wq, Aq, bq, Wk, Ak, bk);
    proj_mma_kernel<<<dim3(8, 16, 3), 256, MT_SMEM>>>(bv);
    scores_kernel<<<dim3(64, Hd, Bd), 256, SC_SMEM>>>(av, attn_out);
    out_mma_kernel<<<dim3(8, 16), 256, MT_SMEM>>>(bo, out);
}